// round 15
// baseline (speedup 1.0000x reference)
#include <cuda_runtime.h>
#include <cstdint>

// ---------------------------------------------------------------------------
// R14: R13 (best, 114.7us) + exactly ONE change: phase-3 restructure.
//   * thread owns 1 channel x 4-px half-row (16ch x 4row x 2half = 128 thr)
//   * x loads: 3 aligned LDS.128 per tap-row (was 10 LDS.64 w/ 4-way conflicts)
//   * wg loads: broadcast float4 per tap (was float2)
//   * halo channel stride padded 160 -> 168 floats (breaks bank aliasing)
// Kernel A and all other kernel-B phases unchanged (R13 verbatim).
// ---------------------------------------------------------------------------

#define U64 unsigned long long

__device__ __forceinline__ U64 ffma2(U64 a, U64 b, U64 c) {
    U64 d;
    asm("fma.rn.f32x2 %0, %1, %2, %3;" : "=l"(d) : "l"(a), "l"(b), "l"(c));
    return d;
}
__device__ __forceinline__ U64 pack2(float lo, float hi) {
    U64 d;
    asm("mov.b64 %0, {%1, %2};" : "=l"(d) : "f"(lo), "f"(hi));
    return d;
}
__device__ __forceinline__ float2 unpack2(U64 v) {
    float2 r;
    asm("mov.b64 {%0, %1}, %2;" : "=f"(r.x), "=f"(r.y) : "l"(v));
    return r;
}
__device__ __forceinline__ void cp_async16(void* s, const void* g) {
    uint32_t sa = (uint32_t)__cvta_generic_to_shared(s);
    asm volatile("cp.async.cg.shared.global [%0], [%1], 16;" :: "r"(sa), "l"(g));
}
__device__ __forceinline__ void cp_async16z(void* s, const void* g, int srcbytes) {
    uint32_t sa = (uint32_t)__cvta_generic_to_shared(s);
    asm volatile("cp.async.cg.shared.global [%0], [%1], 16, %2;"
                 :: "r"(sa), "l"(g), "r"(srcbytes));
}
__device__ __forceinline__ void cp_commit()  { asm volatile("cp.async.commit_group;"); }
__device__ __forceinline__ void cp_wait1()   { asm volatile("cp.async.wait_group 1;"); }
__device__ __forceinline__ void cp_wait0()   { asm volatile("cp.async.wait_group 0;"); }

namespace cfg {
constexpr int C   = 256;
constexpr int HW  = 56;
constexpr int G   = 16;
constexpr int Cg  = 16;
constexpr int KS  = 7;
constexpr int PAD = 3;
constexpr int CR  = 64;
constexpr float EPSV = 1e-5f;

constexpr int TH = 4, TW = 8;
constexpr int TP = TH * TW;               // 32 pixels / tile
constexpr int HALO_H  = TH + 2 * PAD;     // 10 rows
constexpr int HALO_WP = 16;               // padded row width, base col = w0-4
constexpr int HALO_CH = 168;              // channel stride (10*16 + 8 pad) — bank spread
constexpr int SPLIT = 16;                 // ONE group per block

// Kernel A smem: W1d float4[64][33] + xs[64][32]  (R7 verbatim)
constexpr int W1D_ROW  = 33;
constexpr int A_OFF_XS = 64 * W1D_ROW * 4;         // 8448
constexpr int A_SMEM_FLOATS = A_OFF_XS + 2048;     // 10496 = 41 KiB

// Kernel B smem
constexpr int B_OFF_TS  = 0;                              // ts[64][32] 2048
constexpr int W2D_ROW   = 26;                             // float4 units (pair 25 = 0)
constexpr int B_OFF_W2D = 2048;                           // 64*26*4 = 6656
constexpr int B_OFF_WG  = B_OFF_W2D + 64 * W2D_ROW * 4;   // 8704
constexpr int B_OFF_XH  = B_OFF_WG + 49 * TP;             // 10272
constexpr int B_SMEM_FLOATS = B_OFF_XH + Cg * HALO_CH;    // 12960 = 50.6 KiB
}
using namespace cfg;

__device__ float t_buf[4 * CR * HW * HW];   // 3.2 MB scratch

// ===========================================================================
// Kernel A: t = relu(BN(x @ W1^T + b1)), R7/R13 version verbatim
// ===========================================================================
__global__ void __launch_bounds__(256) t_gemm_kernel(
    const float* __restrict__ x,
    const float* __restrict__ W1, const float* __restrict__ b1,
    const float* __restrict__ gamma, const float* __restrict__ beta,
    const float* __restrict__ mean, const float* __restrict__ var)
{
    extern __shared__ float smem[];
    ulonglong2* W1d = (ulonglong2*)smem;    // [cc][33]: pair p = (W1[2p] dup | W1[2p+1] dup)
    float* xs = smem + A_OFF_XS;            // [64ch][32px]

    const int tid = threadIdx.x;
    const int b   = blockIdx.z;
    const int h0  = blockIdx.y * TH;
    const int w0  = blockIdx.x * TW;
    const int oq  = tid >> 3;               // active oq<16: outs 4oq..4oq+3
    const int pxq = tid & 7;                // px 4pxq..4pxq+3
    U64 q0a = 0, q0b = 0, q1a = 0, q1b = 0, q2a = 0, q2b = 0, q3a = 0, q3b = 0;

    for (int chunk = 0; chunk < 4; chunk++) {
        const int c0 = chunk * 64;
        {
            int idx = tid;
            #pragma unroll
            for (int r = 0; r < 2; r++) {
                const int cc = idx >> 3, py = (idx >> 1) & 3, hf = idx & 1;
                const float4 v = *(const float4*)&x[((b * C + c0 + cc) * HW + h0 + py) * HW + w0 + hf * 4];
                *(float4*)&xs[cc * TP + py * TW + hf * 4] = v;
                idx += 256;
            }
        }
        #pragma unroll
        for (int r = 0; r < 8; r++) {
            const int idx = tid + 256 * r;
            const int cc = idx & 63, o2 = idx >> 6;     // pair o2: 0..31
            const float v0 = __ldg(&W1[(2 * o2) * C + c0 + cc]);
            const float v1 = __ldg(&W1[(2 * o2 + 1) * C + c0 + cc]);
            *(float4*)&W1d[cc * W1D_ROW + o2] = make_float4(v0, v0, v1, v1);
        }
        __syncthreads();

        if (oq < 16) {
            #pragma unroll 8
            for (int cc = 0; cc < 64; cc++) {
                const ulonglong2 tv  = *(const ulonglong2*)&xs[cc * TP + pxq * 4];
                const ulonglong2 wva = W1d[cc * W1D_ROW + 2 * oq];
                const ulonglong2 wvb = W1d[cc * W1D_ROW + 2 * oq + 1];
                q0a = ffma2(wva.x, tv.x, q0a); q0b = ffma2(wva.x, tv.y, q0b);
                q1a = ffma2(wva.y, tv.x, q1a); q1b = ffma2(wva.y, tv.y, q1b);
                q2a = ffma2(wvb.x, tv.x, q2a); q2b = ffma2(wvb.x, tv.y, q2b);
                q3a = ffma2(wvb.y, tv.x, q3a); q3b = ffma2(wvb.y, tv.y, q3b);
            }
        }
        __syncthreads();
    }

    if (oq < 16) {
        const int py = pxq >> 1, pw = (pxq & 1) * 4;
        U64 qa[4] = {q0a, q1a, q2a, q3a};
        U64 qb[4] = {q0b, q1b, q2b, q3b};
        #pragma unroll
        for (int u = 0; u < 4; u++) {
            const int o = 4 * oq + u;
            const float a  = __ldg(&gamma[o]) * rsqrtf(__ldg(&var[o]) + EPSV);
            const float bb = __ldg(&b1[o]) * a + __ldg(&beta[o]) - __ldg(&mean[o]) * a;
            const float2 p0 = unpack2(qa[u]);
            const float2 p1 = unpack2(qb[u]);
            float4 r;
            r.x = fmaxf(p0.x * a + bb, 0.f);
            r.y = fmaxf(p0.y * a + bb, 0.f);
            r.z = fmaxf(p1.x * a + bb, 0.f);
            r.w = fmaxf(p1.y * a + bb, 0.f);
            *(float4*)&t_buf[((b * CR + o) * HW + h0 + py) * HW + w0 + pw] = r;
        }
    }
}

// ===========================================================================
// Kernel B: kernel-GEMM + involution, ONE group per block
// ===========================================================================
__global__ void __launch_bounds__(256) involution_kernel(
    const float* __restrict__ x,
    const float* __restrict__ W2, const float* __restrict__ b2,
    float* __restrict__ out)
{
    extern __shared__ float smem[];
    float* ts = smem + B_OFF_TS;                       // [64cc][32px]
    ulonglong2* W2d = (ulonglong2*)(smem + B_OFF_W2D); // [cc][26] dup pairs
    float* wg = smem + B_OFF_WG;                       // [49k][32px]
    float* xh = smem + B_OFF_XH;                       // [16c][stride 168]

    const int tid = threadIdx.x;
    const int z   = blockIdx.z;
    const int b   = z >> 4;            // batch
    const int g   = z & 15;            // group (one per block)
    const int h0  = blockIdx.y * TH;
    const int w0  = blockIdx.x * TW;

    // ---- stage ts tile via cp.async16 (512 segments, 2 per thread)
    {
        int idx = tid;
        #pragma unroll
        for (int r = 0; r < 2; r++) {
            const int cc = idx >> 3, py = (idx >> 1) & 3, hf = idx & 1;
            cp_async16(&ts[cc * TP + py * TW + hf * 4],
                       &t_buf[((b * CR + cc) * HW + h0 + py) * HW + w0 + hf * 4]);
            idx += 256;
        }
        cp_commit();
    }

    // ---- stage halo: [16c][10 rows][4 seg of 16B], buffer col0 = w0-4, zfill
    {
        const float* xgb = &x[(size_t)(b * C + g * Cg) * HW * HW];
        int idx = tid;
        #pragma unroll
        for (int r4 = 0; r4 < 3; r4++) {       // 640 segments
            if (idx < Cg * HALO_H * 4) {
                const int c   = idx / 40;      // 10 rows * 4 segs
                const int rem = idx - c * 40;
                const int rr  = rem >> 2;
                const int s   = rem & 3;
                const int gh  = h0 + rr - PAD;
                const int gw0 = w0 - 4 + 4 * s;
                int szb = 0;
                if ((unsigned)gh < (unsigned)HW && gw0 >= 0) {
                    const int rem2 = HW - gw0;
                    szb = (rem2 >= 4 ? 4 : (rem2 > 0 ? rem2 : 0)) * 4;
                }
                const int ghc = gh < 0 ? 0 : (gh > HW - 1 ? HW - 1 : gh);
                const int gwc = gw0 < 0 ? 0 : (gw0 > HW - 4 ? HW - 4 : gw0);
                cp_async16z(&xh[c * HALO_CH + rr * HALO_WP + 4 * s],
                            &xgb[(c * HW + ghc) * HW + gwc], szb);
            }
            idx += 256;
        }
        cp_commit();
    }

    // ---- stage W2 group -> W2d[cc][p] = (w_{2p} x2, w_{2p+1} x2), pairs>=25 -> 0
    {
        int idx = tid;
        #pragma unroll
        for (int r = 0; r < 7; r++) {          // 64*26 = 1664
            if (idx < 1664) {
                const int cc = idx & 63, p = idx >> 6;
                const int k0 = 2 * p, k1 = 2 * p + 1;
                const float v0 = (k0 < 49) ? __ldg(&W2[(g * 49 + k0) * CR + cc]) : 0.f;
                const float v1 = (k1 < 49) ? __ldg(&W2[(g * 49 + k1) * CR + cc]) : 0.f;
                *(float4*)&W2d[cc * W2D_ROW + p] = make_float4(v0, v0, v1, v1);
            }
            idx += 256;
        }
    }
    cp_wait1();            // ts landed; halo may still be in flight
    __syncthreads();

    // ---- phase 2: wg[k][p] = sum_cc W2g[k][cc]*t[cc][p] + b2[k]
    {
        const int kq   = tid >> 3;
        const int pxq2 = tid & 7;
        if (kq < 13) {
            const int kbase = 4 * kq;
            float zb[4];
            #pragma unroll
            for (int kk = 0; kk < 4; kk++) {
                const int k = kbase + kk;
                zb[kk] = (k < 49) ? __ldg(&b2[g * 49 + k]) : 0.f;
            }
            U64 q0a = pack2(zb[0], zb[0]), q0b = q0a;
            U64 q1a = pack2(zb[1], zb[1]), q1b = q1a;
            U64 q2a = pack2(zb[2], zb[2]), q2b = q2a;
            U64 q3a = pack2(zb[3], zb[3]), q3b = q3a;
            #pragma unroll 8
            for (int cc = 0; cc < 64; cc++) {
                const ulonglong2 tv  = *(const ulonglong2*)&ts[cc * TP + pxq2 * 4];
                const ulonglong2 wva = W2d[cc * W2D_ROW + 2 * kq];
                const ulonglong2 wvb = W2d[cc * W2D_ROW + 2 * kq + 1];
                q0a = ffma2(wva.x, tv.x, q0a); q0b = ffma2(wva.x, tv.y, q0b);
                q1a = ffma2(wva.y, tv.x, q1a); q1b = ffma2(wva.y, tv.y, q1b);
                q2a = ffma2(wvb.x, tv.x, q2a); q2b = ffma2(wvb.x, tv.y, q2b);
                q3a = ffma2(wvb.y, tv.x, q3a); q3b = ffma2(wvb.y, tv.y, q3b);
            }
            U64 qa[4] = {q0a, q1a, q2a, q3a};
            U64 qb[4] = {q0b, q1b, q2b, q3b};
            #pragma unroll
            for (int kk = 0; kk < 4; kk++) {
                const int k = kbase + kk;
                if (k < 49) {
                    *(U64*)&wg[k * TP + pxq2 * 4]     = qa[kk];
                    *(U64*)&wg[k * TP + pxq2 * 4 + 2] = qb[kk];
                }
            }
        }
    }
    cp_wait0();            // halo landed (overlapped with phase 2)
    __syncthreads();

    // ---- phase 3: threads 0..127 own (1 channel, 4-px half-row)
    //      ch = tid>>3 (0..15), s = tid&7: row3 = s>>1, colh = (s&1)*4
    if (tid < 128) {
        const int ch   = tid >> 3;
        const int s    = tid & 7;
        const int row3 = s >> 1;
        const int colh = (s & 1) * 4;
        const float* xbase = &xh[ch * HALO_CH + row3 * HALO_WP + colh];
        float o0 = 0.f, o1 = 0.f, o2 = 0.f, o3 = 0.f;
        #pragma unroll
        for (int i = 0; i < KS; i++) {
            const float* r0 = xbase + i * HALO_WP;
            const float4 va = *(const float4*)(r0);
            const float4 vb = *(const float4*)(r0 + 4);
            const float4 vc = *(const float4*)(r0 + 8);
            float xr[12];
            xr[0] = va.x; xr[1] = va.y; xr[2]  = va.z; xr[3]  = va.w;
            xr[4] = vb.x; xr[5] = vb.y; xr[6]  = vb.z; xr[7]  = vb.w;
            xr[8] = vc.x; xr[9] = vc.y; xr[10] = vc.z; xr[11] = vc.w;
            #pragma unroll
            for (int j = 0; j < KS; j++) {
                const float4 wv = *(const float4*)&wg[(i * KS + j) * TP + row3 * 8 + colh];
                o0 = fmaf(xr[j + 1], wv.x, o0);
                o1 = fmaf(xr[j + 2], wv.y, o1);
                o2 = fmaf(xr[j + 3], wv.z, o2);
                o3 = fmaf(xr[j + 4], wv.w, o3);
            }
        }
        *(float4*)&out[((b * C + g * Cg + ch) * HW + h0 + row3) * HW + w0 + colh] =
            make_float4(o0, o1, o2, o3);
    }
}

extern "C" void kernel_launch(void* const* d_in, const int* in_sizes, int n_in,
                              void* d_out, int out_size) {
    const float* x     = (const float*)d_in[0];
    const float* W1    = (const float*)d_in[1];
    const float* b1    = (const float*)d_in[2];
    const float* gamma = (const float*)d_in[3];
    const float* beta  = (const float*)d_in[4];
    const float* mean  = (const float*)d_in[5];
    const float* var   = (const float*)d_in[6];
    const float* W2    = (const float*)d_in[7];
    const float* b2    = (const float*)d_in[8];
    float* out = (float*)d_out;

    const size_t smemA = (size_t)A_SMEM_FLOATS * sizeof(float);
    const size_t smemB = (size_t)B_SMEM_FLOATS * sizeof(float);
    cudaFuncSetAttribute(t_gemm_kernel,
                         cudaFuncAttributeMaxDynamicSharedMemorySize, (int)smemA);
    cudaFuncSetAttribute(involution_kernel,
                         cudaFuncAttributeMaxDynamicSharedMemorySize, (int)smemB);

    dim3 gridA(HW / TW, HW / TH, 4);            // 392 blocks
    t_gemm_kernel<<<gridA, 256, smemA>>>(x, W1, b1, gamma, beta, mean, var);

    dim3 gridB(HW / TW, HW / TH, 4 * SPLIT);    // 6272 blocks
    involution_kernel<<<gridB, 256, smemB>>>(x, W2, b2, out);
}

// round 16
// speedup vs baseline: 1.0767x; 1.0767x over previous
#include <cuda_runtime.h>
#include <cstdint>

// ---------------------------------------------------------------------------
// R15: R13 (best, 114.7us) + ONE structural change:
//   W2 dup layout precomputed ONCE into a __device__ buffer (426 KB, L2
//   resident) by a tiny prep kernel; kernel B stages it with linear
//   cp.async16 (6.5/thread) instead of 3328 scattered LDG.32 + 1664 STS +
//   dup math per block. Commit order ts -> W2 -> halo so wait_group 1
//   releases phase 2 with the halo still in flight.
// Kernel A and all other kernel-B phases are R13 verbatim.
// ---------------------------------------------------------------------------

#define U64 unsigned long long

__device__ __forceinline__ U64 ffma2(U64 a, U64 b, U64 c) {
    U64 d;
    asm("fma.rn.f32x2 %0, %1, %2, %3;" : "=l"(d) : "l"(a), "l"(b), "l"(c));
    return d;
}
__device__ __forceinline__ U64 pack2(float lo, float hi) {
    U64 d;
    asm("mov.b64 %0, {%1, %2};" : "=l"(d) : "f"(lo), "f"(hi));
    return d;
}
__device__ __forceinline__ float2 unpack2(U64 v) {
    float2 r;
    asm("mov.b64 {%0, %1}, %2;" : "=f"(r.x), "=f"(r.y) : "l"(v));
    return r;
}
__device__ __forceinline__ void cp_async16(void* s, const void* g) {
    uint32_t sa = (uint32_t)__cvta_generic_to_shared(s);
    asm volatile("cp.async.cg.shared.global [%0], [%1], 16;" :: "r"(sa), "l"(g));
}
__device__ __forceinline__ void cp_async16z(void* s, const void* g, int srcbytes) {
    uint32_t sa = (uint32_t)__cvta_generic_to_shared(s);
    asm volatile("cp.async.cg.shared.global [%0], [%1], 16, %2;"
                 :: "r"(sa), "l"(g), "r"(srcbytes));
}
__device__ __forceinline__ void cp_commit()  { asm volatile("cp.async.commit_group;"); }
__device__ __forceinline__ void cp_wait1()   { asm volatile("cp.async.wait_group 1;"); }
__device__ __forceinline__ void cp_wait0()   { asm volatile("cp.async.wait_group 0;"); }

namespace cfg {
constexpr int C   = 256;
constexpr int HW  = 56;
constexpr int G   = 16;
constexpr int Cg  = 16;
constexpr int KS  = 7;
constexpr int PAD = 3;
constexpr int CR  = 64;
constexpr float EPSV = 1e-5f;

constexpr int TH = 4, TW = 8;
constexpr int TP = TH * TW;               // 32 pixels / tile
constexpr int HALO_H  = TH + 2 * PAD;     // 10 rows
constexpr int HALO_WP = 16;               // padded width, base col = w0-4
constexpr int HALO_CH = HALO_H * HALO_WP; // 160 floats per channel
constexpr int SPLIT = 16;                 // ONE group per block

constexpr int W2D_ROW = 26;               // float4 units per cc row
constexpr int W2D_UNITS = 64 * W2D_ROW;   // 1664 float4 per group

// Kernel A smem: W1d float4[64][33] + xs[64][32]
constexpr int W1D_ROW  = 33;
constexpr int A_OFF_XS = 64 * W1D_ROW * 4;         // 8448
constexpr int A_SMEM_FLOATS = A_OFF_XS + 2048;     // 10496 = 41 KiB

// Kernel B smem (R13 layout)
constexpr int B_OFF_TS  = 0;                              // ts[64][32] 2048
constexpr int B_OFF_W2D = 2048;                           // 64*26*4 = 6656
constexpr int B_OFF_WG  = B_OFF_W2D + W2D_UNITS * 4;      // 8704
constexpr int B_OFF_XH  = B_OFF_WG + 49 * TP;             // 10272
constexpr int B_SMEM_FLOATS = B_OFF_XH + Cg * HALO_CH;    // 12832 = 50.125 KiB
}
using namespace cfg;

__device__ float t_buf[4 * CR * HW * HW];        // 3.2 MB scratch
__device__ float4 w2dup_buf[G * W2D_UNITS];      // 426 KB: [g][cc][26] dup pairs

// ===========================================================================
// Prep kernel: w2dup_buf[g][cc][p] = (W2[g*49+2p][cc] x2, W2[g*49+2p+1][cc] x2)
// ===========================================================================
__global__ void __launch_bounds__(256) w2_prep_kernel(const float* __restrict__ W2)
{
    const int g = blockIdx.x;
    for (int u = threadIdx.x; u < W2D_UNITS; u += 256) {
        const int cc = u / W2D_ROW;
        const int p  = u - cc * W2D_ROW;
        const int k0 = 2 * p, k1 = 2 * p + 1;
        const float v0 = (k0 < 49) ? __ldg(&W2[(g * 49 + k0) * CR + cc]) : 0.f;
        const float v1 = (k1 < 49) ? __ldg(&W2[(g * 49 + k1) * CR + cc]) : 0.f;
        w2dup_buf[g * W2D_UNITS + cc * W2D_ROW + p] = make_float4(v0, v0, v1, v1);
    }
}

// ===========================================================================
// Kernel A: t = relu(BN(x @ W1^T + b1)), R13 verbatim
// ===========================================================================
__global__ void __launch_bounds__(256) t_gemm_kernel(
    const float* __restrict__ x,
    const float* __restrict__ W1, const float* __restrict__ b1,
    const float* __restrict__ gamma, const float* __restrict__ beta,
    const float* __restrict__ mean, const float* __restrict__ var)
{
    extern __shared__ float smem[];
    ulonglong2* W1d = (ulonglong2*)smem;    // [cc][33]: pair p = (W1[2p] dup | W1[2p+1] dup)
    float* xs = smem + A_OFF_XS;            // [64ch][32px]

    const int tid = threadIdx.x;
    const int b   = blockIdx.z;
    const int h0  = blockIdx.y * TH;
    const int w0  = blockIdx.x * TW;
    const int oq  = tid >> 3;               // active oq<16: outs 4oq..4oq+3
    const int pxq = tid & 7;                // px 4pxq..4pxq+3
    U64 q0a = 0, q0b = 0, q1a = 0, q1b = 0, q2a = 0, q2b = 0, q3a = 0, q3b = 0;

    for (int chunk = 0; chunk < 4; chunk++) {
        const int c0 = chunk * 64;
        {
            int idx = tid;
            #pragma unroll
            for (int r = 0; r < 2; r++) {
                const int cc = idx >> 3, py = (idx >> 1) & 3, hf = idx & 1;
                const float4 v = *(const float4*)&x[((b * C + c0 + cc) * HW + h0 + py) * HW + w0 + hf * 4];
                *(float4*)&xs[cc * TP + py * TW + hf * 4] = v;
                idx += 256;
            }
        }
        #pragma unroll
        for (int r = 0; r < 8; r++) {
            const int idx = tid + 256 * r;
            const int cc = idx & 63, o2 = idx >> 6;     // pair o2: 0..31
            const float v0 = __ldg(&W1[(2 * o2) * C + c0 + cc]);
            const float v1 = __ldg(&W1[(2 * o2 + 1) * C + c0 + cc]);
            *(float4*)&W1d[cc * W1D_ROW + o2] = make_float4(v0, v0, v1, v1);
        }
        __syncthreads();

        if (oq < 16) {
            #pragma unroll 8
            for (int cc = 0; cc < 64; cc++) {
                const ulonglong2 tv  = *(const ulonglong2*)&xs[cc * TP + pxq * 4];
                const ulonglong2 wva = W1d[cc * W1D_ROW + 2 * oq];
                const ulonglong2 wvb = W1d[cc * W1D_ROW + 2 * oq + 1];
                q0a = ffma2(wva.x, tv.x, q0a); q0b = ffma2(wva.x, tv.y, q0b);
                q1a = ffma2(wva.y, tv.x, q1a); q1b = ffma2(wva.y, tv.y, q1b);
                q2a = ffma2(wvb.x, tv.x, q2a); q2b = ffma2(wvb.x, tv.y, q2b);
                q3a = ffma2(wvb.y, tv.x, q3a); q3b = ffma2(wvb.y, tv.y, q3b);
            }
        }
        __syncthreads();
    }

    if (oq < 16) {
        const int py = pxq >> 1, pw = (pxq & 1) * 4;
        U64 qa[4] = {q0a, q1a, q2a, q3a};
        U64 qb[4] = {q0b, q1b, q2b, q3b};
        #pragma unroll
        for (int u = 0; u < 4; u++) {
            const int o = 4 * oq + u;
            const float a  = __ldg(&gamma[o]) * rsqrtf(__ldg(&var[o]) + EPSV);
            const float bb = __ldg(&b1[o]) * a + __ldg(&beta[o]) - __ldg(&mean[o]) * a;
            const float2 p0 = unpack2(qa[u]);
            const float2 p1 = unpack2(qb[u]);
            float4 r;
            r.x = fmaxf(p0.x * a + bb, 0.f);
            r.y = fmaxf(p0.y * a + bb, 0.f);
            r.z = fmaxf(p1.x * a + bb, 0.f);
            r.w = fmaxf(p1.y * a + bb, 0.f);
            *(float4*)&t_buf[((b * CR + o) * HW + h0 + py) * HW + w0 + pw] = r;
        }
    }
}

// ===========================================================================
// Kernel B: kernel-GEMM + involution, ONE group per block
// ===========================================================================
__global__ void __launch_bounds__(256) involution_kernel(
    const float* __restrict__ x,
    const float* __restrict__ b2,
    float* __restrict__ out)
{
    extern __shared__ float smem[];
    float* ts = smem + B_OFF_TS;                       // [64cc][32px]
    ulonglong2* W2d = (ulonglong2*)(smem + B_OFF_W2D); // [cc][26] dup pairs
    float* wg = smem + B_OFF_WG;                       // [49k][32px]
    float* xh = smem + B_OFF_XH;                       // [16c][10][16]

    const int tid = threadIdx.x;
    const int z   = blockIdx.z;
    const int b   = z >> 4;            // batch
    const int g   = z & 15;            // group (one per block)
    const int h0  = blockIdx.y * TH;
    const int w0  = blockIdx.x * TW;

    // ---- stage ts tile via cp.async16 (512 segments, 2 per thread) — group 0
    {
        int idx = tid;
        #pragma unroll
        for (int r = 0; r < 2; r++) {
            const int cc = idx >> 3, py = (idx >> 1) & 3, hf = idx & 1;
            cp_async16(&ts[cc * TP + py * TW + hf * 4],
                       &t_buf[((b * CR + cc) * HW + h0 + py) * HW + w0 + hf * 4]);
            idx += 256;
        }
        cp_commit();
    }

    // ---- stage W2d via linear cp.async16 from precomputed buffer — group 1
    {
        const float4* src = &w2dup_buf[g * W2D_UNITS];
        float4* dst = (float4*)W2d;
        int idx = tid;
        #pragma unroll
        for (int r = 0; r < 7; r++) {          // 1664 units
            if (idx < W2D_UNITS) cp_async16(&dst[idx], &src[idx]);
            idx += 256;
        }
        cp_commit();
    }

    // ---- stage halo: [16c][10 rows][4 seg of 16B], col0 = w0-4, zfill — group 2
    {
        const float* xgb = &x[(size_t)(b * C + g * Cg) * HW * HW];
        int idx = tid;
        #pragma unroll
        for (int r4 = 0; r4 < 3; r4++) {       // 640 segments
            if (idx < Cg * HALO_H * 4) {
                const int c   = idx / 40;      // 10 rows * 4 segs
                const int rem = idx - c * 40;
                const int rr  = rem >> 2;
                const int s   = rem & 3;
                const int gh  = h0 + rr - PAD;
                const int gw0 = w0 - 4 + 4 * s;
                int szb = 0;
                if ((unsigned)gh < (unsigned)HW && gw0 >= 0) {
                    const int rem2 = HW - gw0;
                    szb = (rem2 >= 4 ? 4 : (rem2 > 0 ? rem2 : 0)) * 4;
                }
                const int ghc = gh < 0 ? 0 : (gh > HW - 1 ? HW - 1 : gh);
                const int gwc = gw0 < 0 ? 0 : (gw0 > HW - 4 ? HW - 4 : gw0);
                cp_async16z(&xh[c * HALO_CH + rr * HALO_WP + 4 * s],
                            &xgb[(c * HW + ghc) * HW + gwc], szb);
            }
            idx += 256;
        }
        cp_commit();
    }

    cp_wait1();            // ts + W2d landed; halo may still be in flight
    __syncthreads();

    // ---- phase 2: wg[k][p] = sum_cc W2g[k][cc]*t[cc][p] + b2[k]
    {
        const int kq   = tid >> 3;
        const int pxq2 = tid & 7;
        if (kq < 13) {
            const int kbase = 4 * kq;
            float zb[4];
            #pragma unroll
            for (int kk = 0; kk < 4; kk++) {
                const int k = kbase + kk;
                zb[kk] = (k < 49) ? __ldg(&b2[g * 49 + k]) : 0.f;
            }
            U64 q0a = pack2(zb[0], zb[0]), q0b = q0a;
            U64 q1a = pack2(zb[1], zb[1]), q1b = q1a;
            U64 q2a = pack2(zb[2], zb[2]), q2b = q2a;
            U64 q3a = pack2(zb[3], zb[3]), q3b = q3a;
            #pragma unroll 8
            for (int cc = 0; cc < 64; cc++) {
                const ulonglong2 tv  = *(const ulonglong2*)&ts[cc * TP + pxq2 * 4];
                const ulonglong2 wva = W2d[cc * W2D_ROW + 2 * kq];
                const ulonglong2 wvb = W2d[cc * W2D_ROW + 2 * kq + 1];
                q0a = ffma2(wva.x, tv.x, q0a); q0b = ffma2(wva.x, tv.y, q0b);
                q1a = ffma2(wva.y, tv.x, q1a); q1b = ffma2(wva.y, tv.y, q1b);
                q2a = ffma2(wvb.x, tv.x, q2a); q2b = ffma2(wvb.x, tv.y, q2b);
                q3a = ffma2(wvb.y, tv.x, q3a); q3b = ffma2(wvb.y, tv.y, q3b);
            }
            U64 qa[4] = {q0a, q1a, q2a, q3a};
            U64 qb[4] = {q0b, q1b, q2b, q3b};
            #pragma unroll
            for (int kk = 0; kk < 4; kk++) {
                const int k = kbase + kk;
                if (k < 49) {
                    *(U64*)&wg[k * TP + pxq2 * 4]     = qa[kk];
                    *(U64*)&wg[k * TP + pxq2 * 4 + 2] = qb[kk];
                }
            }
        }
    }
    cp_wait0();            // halo landed (overlapped with phase 2)
    __syncthreads();

    // ---- phase 3: threads 0..127 own (channels 2cs,2cs+1; pixels 2pxp,2pxp+1)
    if (tid < 128) {
        const int cs   = tid >> 4;
        const int pxp  = tid & 15;
        const int py3  = pxp >> 2;
        const int col3 = (pxp & 3) * 2;
        const int c0 = 2 * cs;
        const float* xa = &xh[c0 * HALO_CH + py3 * HALO_WP + col3];
        const float* xb = xa + HALO_CH;
        float o00 = 0.f, o01 = 0.f, o10 = 0.f, o11 = 0.f;
        #pragma unroll
        for (int i = 0; i < KS; i++) {
            const float* r0 = xa + i * HALO_WP;
            const float* r1 = xb + i * HALO_WP;
            float x0[10], x1[10];
            #pragma unroll
            for (int q = 0; q < 5; q++) {
                const float2 v0 = *(const float2*)(r0 + 2 * q);
                const float2 v1 = *(const float2*)(r1 + 2 * q);
                x0[2 * q] = v0.x; x0[2 * q + 1] = v0.y;
                x1[2 * q] = v1.x; x1[2 * q + 1] = v1.y;
            }
            #pragma unroll
            for (int j = 0; j < KS; j++) {
                const float2 wv = *(const float2*)&wg[(i * KS + j) * TP + 2 * pxp];
                o00 = fmaf(x0[j + 1], wv.x, o00);
                o01 = fmaf(x0[j + 2], wv.y, o01);
                o10 = fmaf(x1[j + 1], wv.x, o10);
                o11 = fmaf(x1[j + 2], wv.y, o11);
            }
        }
        const int base = ((b * C + g * Cg + c0) * HW + h0 + py3) * HW + w0 + col3;
        *(float2*)&out[base]           = make_float2(o00, o01);
        *(float2*)&out[base + HW * HW] = make_float2(o10, o11);
    }
}

extern "C" void kernel_launch(void* const* d_in, const int* in_sizes, int n_in,
                              void* d_out, int out_size) {
    const float* x     = (const float*)d_in[0];
    const float* W1    = (const float*)d_in[1];
    const float* b1    = (const float*)d_in[2];
    const float* gamma = (const float*)d_in[3];
    const float* beta  = (const float*)d_in[4];
    const float* mean  = (const float*)d_in[5];
    const float* var   = (const float*)d_in[6];
    const float* W2    = (const float*)d_in[7];
    const float* b2    = (const float*)d_in[8];
    float* out = (float*)d_out;

    const size_t smemA = (size_t)A_SMEM_FLOATS * sizeof(float);
    const size_t smemB = (size_t)B_SMEM_FLOATS * sizeof(float);
    cudaFuncSetAttribute(t_gemm_kernel,
                         cudaFuncAttributeMaxDynamicSharedMemorySize, (int)smemA);
    cudaFuncSetAttribute(involution_kernel,
                         cudaFuncAttributeMaxDynamicSharedMemorySize, (int)smemB);

    w2_prep_kernel<<<G, 256>>>(W2);                       // 426 KB dup image

    dim3 gridA(HW / TW, HW / TH, 4);            // 392 blocks
    t_gemm_kernel<<<gridA, 256, smemA>>>(x, W1, b1, gamma, beta, mean, var);

    dim3 gridB(HW / TW, HW / TH, 4 * SPLIT);    // 6272 blocks
    involution_kernel<<<gridB, 256, smemB>>>(x, b2, out);
}

// round 17
// speedup vs baseline: 1.1003x; 1.0220x over previous
#include <cuda_runtime.h>
#include <cstdint>

// ---------------------------------------------------------------------------
// R16: R15 (best, 107.2us) + ONE change: the W2-dup prep is folded into
// kernel A's grid as a 5th z-slice (98 blocks), eliminating the separate
// 6.5us prep launch — prep overlaps with the latency-bound GEMM blocks.
// Everything else is R15 verbatim.
// ---------------------------------------------------------------------------

#define U64 unsigned long long

__device__ __forceinline__ U64 ffma2(U64 a, U64 b, U64 c) {
    U64 d;
    asm("fma.rn.f32x2 %0, %1, %2, %3;" : "=l"(d) : "l"(a), "l"(b), "l"(c));
    return d;
}
__device__ __forceinline__ U64 pack2(float lo, float hi) {
    U64 d;
    asm("mov.b64 %0, {%1, %2};" : "=l"(d) : "f"(lo), "f"(hi));
    return d;
}
__device__ __forceinline__ float2 unpack2(U64 v) {
    float2 r;
    asm("mov.b64 {%0, %1}, %2;" : "=f"(r.x), "=f"(r.y) : "l"(v));
    return r;
}
__device__ __forceinline__ void cp_async16(void* s, const void* g) {
    uint32_t sa = (uint32_t)__cvta_generic_to_shared(s);
    asm volatile("cp.async.cg.shared.global [%0], [%1], 16;" :: "r"(sa), "l"(g));
}
__device__ __forceinline__ void cp_async16z(void* s, const void* g, int srcbytes) {
    uint32_t sa = (uint32_t)__cvta_generic_to_shared(s);
    asm volatile("cp.async.cg.shared.global [%0], [%1], 16, %2;"
                 :: "r"(sa), "l"(g), "r"(srcbytes));
}
__device__ __forceinline__ void cp_commit()  { asm volatile("cp.async.commit_group;"); }
__device__ __forceinline__ void cp_wait1()   { asm volatile("cp.async.wait_group 1;"); }
__device__ __forceinline__ void cp_wait0()   { asm volatile("cp.async.wait_group 0;"); }

namespace cfg {
constexpr int C   = 256;
constexpr int HW  = 56;
constexpr int G   = 16;
constexpr int Cg  = 16;
constexpr int KS  = 7;
constexpr int PAD = 3;
constexpr int CR  = 64;
constexpr float EPSV = 1e-5f;

constexpr int TH = 4, TW = 8;
constexpr int TP = TH * TW;               // 32 pixels / tile
constexpr int HALO_H  = TH + 2 * PAD;     // 10 rows
constexpr int HALO_WP = 16;               // padded width, base col = w0-4
constexpr int HALO_CH = HALO_H * HALO_WP; // 160 floats per channel
constexpr int SPLIT = 16;                 // ONE group per block

constexpr int W2D_ROW = 26;               // float4 units per cc row
constexpr int W2D_UNITS = 64 * W2D_ROW;   // 1664 float4 per group
constexpr int W2D_TOTAL = G * W2D_UNITS;  // 26624 float4 units

// Kernel A smem: W1d float4[64][33] + xs[64][32]
constexpr int W1D_ROW  = 33;
constexpr int A_OFF_XS = 64 * W1D_ROW * 4;         // 8448
constexpr int A_SMEM_FLOATS = A_OFF_XS + 2048;     // 10496 = 41 KiB

// Kernel B smem (R13 layout)
constexpr int B_OFF_TS  = 0;                              // ts[64][32] 2048
constexpr int B_OFF_W2D = 2048;                           // 64*26*4 = 6656
constexpr int B_OFF_WG  = B_OFF_W2D + W2D_UNITS * 4;      // 8704
constexpr int B_OFF_XH  = B_OFF_WG + 49 * TP;             // 10272
constexpr int B_SMEM_FLOATS = B_OFF_XH + Cg * HALO_CH;    // 12832 = 50.125 KiB
}
using namespace cfg;

__device__ float t_buf[4 * CR * HW * HW];        // 3.2 MB scratch
__device__ float4 w2dup_buf[W2D_TOTAL];          // 426 KB: [g][cc][26] dup pairs

// ===========================================================================
// Kernel A: t = relu(BN(x @ W1^T + b1))   [z<4]
//           + W2-dup prep on the z==4 slice (98 blocks, overlapped)
// ===========================================================================
__global__ void __launch_bounds__(256) t_gemm_kernel(
    const float* __restrict__ x,
    const float* __restrict__ W1, const float* __restrict__ b1,
    const float* __restrict__ gamma, const float* __restrict__ beta,
    const float* __restrict__ mean, const float* __restrict__ var,
    const float* __restrict__ W2)
{
    const int tid = threadIdx.x;

    if (blockIdx.z == 4) {
        // ---- W2 dup prep: w2dup_buf[g][cc][p] = (W2[g*49+2p][cc] x2, ...x2)
        const int blk = blockIdx.y * 7 + blockIdx.x;    // 0..97
        int u = blk * 256 + tid;                        // stride 25088
        #pragma unroll
        for (int r = 0; r < 2; r++) {
            if (u < W2D_TOTAL) {
                const int g   = u / W2D_UNITS;
                const int rem = u - g * W2D_UNITS;
                const int cc  = rem / W2D_ROW;
                const int p   = rem - cc * W2D_ROW;
                const int k0 = 2 * p, k1 = 2 * p + 1;
                const float v0 = (k0 < 49) ? __ldg(&W2[(g * 49 + k0) * CR + cc]) : 0.f;
                const float v1 = (k1 < 49) ? __ldg(&W2[(g * 49 + k1) * CR + cc]) : 0.f;
                w2dup_buf[u] = make_float4(v0, v0, v1, v1);
            }
            u += 25088;
        }
        return;
    }

    extern __shared__ float smem[];
    ulonglong2* W1d = (ulonglong2*)smem;    // [cc][33]: pair p = (W1[2p] dup | W1[2p+1] dup)
    float* xs = smem + A_OFF_XS;            // [64ch][32px]

    const int b   = blockIdx.z;
    const int h0  = blockIdx.y * TH;
    const int w0  = blockIdx.x * TW;
    const int oq  = tid >> 3;               // active oq<16: outs 4oq..4oq+3
    const int pxq = tid & 7;                // px 4pxq..4pxq+3
    U64 q0a = 0, q0b = 0, q1a = 0, q1b = 0, q2a = 0, q2b = 0, q3a = 0, q3b = 0;

    for (int chunk = 0; chunk < 4; chunk++) {
        const int c0 = chunk * 64;
        {
            int idx = tid;
            #pragma unroll
            for (int r = 0; r < 2; r++) {
                const int cc = idx >> 3, py = (idx >> 1) & 3, hf = idx & 1;
                const float4 v = *(const float4*)&x[((b * C + c0 + cc) * HW + h0 + py) * HW + w0 + hf * 4];
                *(float4*)&xs[cc * TP + py * TW + hf * 4] = v;
                idx += 256;
            }
        }
        #pragma unroll
        for (int r = 0; r < 8; r++) {
            const int idx = tid + 256 * r;
            const int cc = idx & 63, o2 = idx >> 6;     // pair o2: 0..31
            const float v0 = __ldg(&W1[(2 * o2) * C + c0 + cc]);
            const float v1 = __ldg(&W1[(2 * o2 + 1) * C + c0 + cc]);
            *(float4*)&W1d[cc * W1D_ROW + o2] = make_float4(v0, v0, v1, v1);
        }
        __syncthreads();

        if (oq < 16) {
            #pragma unroll 8
            for (int cc = 0; cc < 64; cc++) {
                const ulonglong2 tv  = *(const ulonglong2*)&xs[cc * TP + pxq * 4];
                const ulonglong2 wva = W1d[cc * W1D_ROW + 2 * oq];
                const ulonglong2 wvb = W1d[cc * W1D_ROW + 2 * oq + 1];
                q0a = ffma2(wva.x, tv.x, q0a); q0b = ffma2(wva.x, tv.y, q0b);
                q1a = ffma2(wva.y, tv.x, q1a); q1b = ffma2(wva.y, tv.y, q1b);
                q2a = ffma2(wvb.x, tv.x, q2a); q2b = ffma2(wvb.x, tv.y, q2b);
                q3a = ffma2(wvb.y, tv.x, q3a); q3b = ffma2(wvb.y, tv.y, q3b);
            }
        }
        __syncthreads();
    }

    if (oq < 16) {
        const int py = pxq >> 1, pw = (pxq & 1) * 4;
        U64 qa[4] = {q0a, q1a, q2a, q3a};
        U64 qb[4] = {q0b, q1b, q2b, q3b};
        #pragma unroll
        for (int u = 0; u < 4; u++) {
            const int o = 4 * oq + u;
            const float a  = __ldg(&gamma[o]) * rsqrtf(__ldg(&var[o]) + EPSV);
            const float bb = __ldg(&b1[o]) * a + __ldg(&beta[o]) - __ldg(&mean[o]) * a;
            const float2 p0 = unpack2(qa[u]);
            const float2 p1 = unpack2(qb[u]);
            float4 r;
            r.x = fmaxf(p0.x * a + bb, 0.f);
            r.y = fmaxf(p0.y * a + bb, 0.f);
            r.z = fmaxf(p1.x * a + bb, 0.f);
            r.w = fmaxf(p1.y * a + bb, 0.f);
            *(float4*)&t_buf[((b * CR + o) * HW + h0 + py) * HW + w0 + pw] = r;
        }
    }
}

// ===========================================================================
// Kernel B: kernel-GEMM + involution, ONE group per block (R15 verbatim)
// ===========================================================================
__global__ void __launch_bounds__(256) involution_kernel(
    const float* __restrict__ x,
    const float* __restrict__ b2,
    float* __restrict__ out)
{
    extern __shared__ float smem[];
    float* ts = smem + B_OFF_TS;                       // [64cc][32px]
    ulonglong2* W2d = (ulonglong2*)(smem + B_OFF_W2D); // [cc][26] dup pairs
    float* wg = smem + B_OFF_WG;                       // [49k][32px]
    float* xh = smem + B_OFF_XH;                       // [16c][10][16]

    const int tid = threadIdx.x;
    const int z   = blockIdx.z;
    const int b   = z >> 4;            // batch
    const int g   = z & 15;            // group (one per block)
    const int h0  = blockIdx.y * TH;
    const int w0  = blockIdx.x * TW;

    // ---- stage ts tile via cp.async16 (512 segments, 2 per thread) — group 0
    {
        int idx = tid;
        #pragma unroll
        for (int r = 0; r < 2; r++) {
            const int cc = idx >> 3, py = (idx >> 1) & 3, hf = idx & 1;
            cp_async16(&ts[cc * TP + py * TW + hf * 4],
                       &t_buf[((b * CR + cc) * HW + h0 + py) * HW + w0 + hf * 4]);
            idx += 256;
        }
        cp_commit();
    }

    // ---- stage W2d via linear cp.async16 from precomputed buffer — group 1
    {
        const float4* src = &w2dup_buf[g * W2D_UNITS];
        float4* dst = (float4*)W2d;
        int idx = tid;
        #pragma unroll
        for (int r = 0; r < 7; r++) {          // 1664 units
            if (idx < W2D_UNITS) cp_async16(&dst[idx], &src[idx]);
            idx += 256;
        }
        cp_commit();
    }

    // ---- stage halo: [16c][10 rows][4 seg of 16B], col0 = w0-4, zfill — group 2
    {
        const float* xgb = &x[(size_t)(b * C + g * Cg) * HW * HW];
        int idx = tid;
        #pragma unroll
        for (int r4 = 0; r4 < 3; r4++) {       // 640 segments
            if (idx < Cg * HALO_H * 4) {
                const int c   = idx / 40;      // 10 rows * 4 segs
                const int rem = idx - c * 40;
                const int rr  = rem >> 2;
                const int s   = rem & 3;
                const int gh  = h0 + rr - PAD;
                const int gw0 = w0 - 4 + 4 * s;
                int szb = 0;
                if ((unsigned)gh < (unsigned)HW && gw0 >= 0) {
                    const int rem2 = HW - gw0;
                    szb = (rem2 >= 4 ? 4 : (rem2 > 0 ? rem2 : 0)) * 4;
                }
                const int ghc = gh < 0 ? 0 : (gh > HW - 1 ? HW - 1 : gh);
                const int gwc = gw0 < 0 ? 0 : (gw0 > HW - 4 ? HW - 4 : gw0);
                cp_async16z(&xh[c * HALO_CH + rr * HALO_WP + 4 * s],
                            &xgb[(c * HW + ghc) * HW + gwc], szb);
            }
            idx += 256;
        }
        cp_commit();
    }

    cp_wait1();            // ts + W2d landed; halo may still be in flight
    __syncthreads();

    // ---- phase 2: wg[k][p] = sum_cc W2g[k][cc]*t[cc][p] + b2[k]
    {
        const int kq   = tid >> 3;
        const int pxq2 = tid & 7;
        if (kq < 13) {
            const int kbase = 4 * kq;
            float zb[4];
            #pragma unroll
            for (int kk = 0; kk < 4; kk++) {
                const int k = kbase + kk;
                zb[kk] = (k < 49) ? __ldg(&b2[g * 49 + k]) : 0.f;
            }
            U64 q0a = pack2(zb[0], zb[0]), q0b = q0a;
            U64 q1a = pack2(zb[1], zb[1]), q1b = q1a;
            U64 q2a = pack2(zb[2], zb[2]), q2b = q2a;
            U64 q3a = pack2(zb[3], zb[3]), q3b = q3a;
            #pragma unroll 8
            for (int cc = 0; cc < 64; cc++) {
                const ulonglong2 tv  = *(const ulonglong2*)&ts[cc * TP + pxq2 * 4];
                const ulonglong2 wva = W2d[cc * W2D_ROW + 2 * kq];
                const ulonglong2 wvb = W2d[cc * W2D_ROW + 2 * kq + 1];
                q0a = ffma2(wva.x, tv.x, q0a); q0b = ffma2(wva.x, tv.y, q0b);
                q1a = ffma2(wva.y, tv.x, q1a); q1b = ffma2(wva.y, tv.y, q1b);
                q2a = ffma2(wvb.x, tv.x, q2a); q2b = ffma2(wvb.x, tv.y, q2b);
                q3a = ffma2(wvb.y, tv.x, q3a); q3b = ffma2(wvb.y, tv.y, q3b);
            }
            U64 qa[4] = {q0a, q1a, q2a, q3a};
            U64 qb[4] = {q0b, q1b, q2b, q3b};
            #pragma unroll
            for (int kk = 0; kk < 4; kk++) {
                const int k = kbase + kk;
                if (k < 49) {
                    *(U64*)&wg[k * TP + pxq2 * 4]     = qa[kk];
                    *(U64*)&wg[k * TP + pxq2 * 4 + 2] = qb[kk];
                }
            }
        }
    }
    cp_wait0();            // halo landed (overlapped with phase 2)
    __syncthreads();

    // ---- phase 3: threads 0..127 own (channels 2cs,2cs+1; pixels 2pxp,2pxp+1)
    if (tid < 128) {
        const int cs   = tid >> 4;
        const int pxp  = tid & 15;
        const int py3  = pxp >> 2;
        const int col3 = (pxp & 3) * 2;
        const int c0 = 2 * cs;
        const float* xa = &xh[c0 * HALO_CH + py3 * HALO_WP + col3];
        const float* xb = xa + HALO_CH;
        float o00 = 0.f, o01 = 0.f, o10 = 0.f, o11 = 0.f;
        #pragma unroll
        for (int i = 0; i < KS; i++) {
            const float* r0 = xa + i * HALO_WP;
            const float* r1 = xb + i * HALO_WP;
            float x0[10], x1[10];
            #pragma unroll
            for (int q = 0; q < 5; q++) {
                const float2 v0 = *(const float2*)(r0 + 2 * q);
                const float2 v1 = *(const float2*)(r1 + 2 * q);
                x0[2 * q] = v0.x; x0[2 * q + 1] = v0.y;
                x1[2 * q] = v1.x; x1[2 * q + 1] = v1.y;
            }
            #pragma unroll
            for (int j = 0; j < KS; j++) {
                const float2 wv = *(const float2*)&wg[(i * KS + j) * TP + 2 * pxp];
                o00 = fmaf(x0[j + 1], wv.x, o00);
                o01 = fmaf(x0[j + 2], wv.y, o01);
                o10 = fmaf(x1[j + 1], wv.x, o10);
                o11 = fmaf(x1[j + 2], wv.y, o11);
            }
        }
        const int base = ((b * C + g * Cg + c0) * HW + h0 + py3) * HW + w0 + col3;
        *(float2*)&out[base]           = make_float2(o00, o01);
        *(float2*)&out[base + HW * HW] = make_float2(o10, o11);
    }
}

extern "C" void kernel_launch(void* const* d_in, const int* in_sizes, int n_in,
                              void* d_out, int out_size) {
    const float* x     = (const float*)d_in[0];
    const float* W1    = (const float*)d_in[1];
    const float* b1    = (const float*)d_in[2];
    const float* gamma = (const float*)d_in[3];
    const float* beta  = (const float*)d_in[4];
    const float* mean  = (const float*)d_in[5];
    const float* var   = (const float*)d_in[6];
    const float* W2    = (const float*)d_in[7];
    const float* b2    = (const float*)d_in[8];
    float* out = (float*)d_out;

    const size_t smemA = (size_t)A_SMEM_FLOATS * sizeof(float);
    const size_t smemB = (size_t)B_SMEM_FLOATS * sizeof(float);
    cudaFuncSetAttribute(t_gemm_kernel,
                         cudaFuncAttributeMaxDynamicSharedMemorySize, (int)smemA);
    cudaFuncSetAttribute(involution_kernel,
                         cudaFuncAttributeMaxDynamicSharedMemorySize, (int)smemB);

    dim3 gridA(HW / TW, HW / TH, 5);            // 392 GEMM blocks + 98 prep blocks
    t_gemm_kernel<<<gridA, 256, smemA>>>(x, W1, b1, gamma, beta, mean, var, W2);

    dim3 gridB(HW / TW, HW / TH, 4 * SPLIT);    // 6272 blocks
    involution_kernel<<<gridB, 256, smemB>>>(x, b2, out);
}